// round 15
// baseline (speedup 1.0000x reference)
#include <cuda_runtime.h>
#include <cuda_bf16.h>
#include <math.h>

// Problem constants
#define BB   16
#define PP   4096
#define MM   1024
#define KK   16
#define FIN  64
#define FOUT 128
#define NN   (BB * PP)          // 65536
#define BN_EPS 1e-5f

#define OFF_P  (BB * MM * FOUT)            // 2097152
#define OFF_B  (OFF_P + BB * MM * 3)       // 2146304
#define TOTAL_OUT (OFF_B + BB * MM)        // 2162688

#define N_MLP_BLOCKS 256
#define N_KNN_BLOCKS 512                    // 8 chunks x 16 clouds x 4 quarters
#define MEGA_BLOCKS  (BB + N_MLP_BLOCKS + N_KNN_BLOCKS)   // 784

// f32x2 packed ops (sm_103a): two independent rn-rounded fp32 ops ->
// bitwise identical to the scalar sequences they replace.
#define PACK2(o, lo, hi)  asm("mov.b64 %0, {%1, %2};" : "=l"(o) : "f"(lo), "f"(hi))
#define UNPACK2(lo, hi, i) asm("mov.b64 {%0, %1}, %2;" : "=f"(lo), "=f"(hi) : "l"(i))
#define FMA2(acc, a, b)   asm("fma.rn.f32x2 %0, %1, %2, %0;" : "+l"(acc) : "l"(a), "l"(b))
#define ADD2(o, a, b)     asm("add.rn.f32x2 %0, %1, %2;" : "=l"(o) : "l"(a), "l"(b))
#define MUL2(o, a, b)     asm("mul.rn.f32x2 %0, %1, %2;" : "=l"(o) : "l"(a), "l"(b))

typedef unsigned long long ull;

static __device__ __forceinline__ ull umax64(ull a, ull b) { return a > b ? a : b; }

// -------- scratch (static device globals; no allocation allowed) --------
__device__ int   g_fps[BB * MM];
__device__ ull   g_keys[(size_t)BB * MM * 64];  // per query: 4 quarters x 16 sorted keys
__device__ float g_h[(size_t)NN * FOUT];        // 33.5 MB pre-BN activations
__device__ float g_psum[1024 * FOUT];           // 1024 x 128 partial sums (64 rows each)
__device__ float g_psq [1024 * FOUT];
__device__ float g_mean[FOUT];
__device__ float g_var [FOUT];
__device__ float g_xx[NN];                      // per-point sum(x*x) in feature space
// cross-block progress (reset by init kernel every call)
__device__ int   g_prog[BB];                    // fps indices published per cloud
__device__ int   g_mlp_done;                    // completed mlp blocks

__global__ void init_kernel()
{
    int t = threadIdx.x;
    if (t < BB) g_prog[t] = 0;
    if (t == 31) g_mlp_done = 0;
}

// ============================================================
// Mega kernel, 512 threads/block:
//   blocks [0,16)    : FPS (one cloud each, publishes progress/128)
//   blocks [16,272)  : MLP (+xx) on 256 rows each, signals done
//   blocks [272,784) : KNN quarter-chunk (128 queries x 1024 candidates),
//                      spins on progress, emits sorted top-16 keys.
// ============================================================
__global__ void __launch_bounds__(512) mega_kernel(
    const float* __restrict__ pos,
    const float* __restrict__ feat,
    const float* __restrict__ W,
    const float* __restrict__ bias)
{
    extern __shared__ float fsm[];
    const int tid = threadIdx.x;
    const int bid = blockIdx.x;

    if (bid < BB) {
        // ---------------- FPS path: 512 thr, 8 pts/thread ----------------
        float* sx = fsm;
        float* sy = fsm + PP;
        float* sz = fsm + 2 * PP;
        uint2* swp = (uint2*)(fsm + 3 * PP);   // double-buffered: 2 x 16

        const int b    = bid;
        const int lane = tid & 31;
        const int wid  = tid >> 5;             // 0..15

        const float* pb = pos + (size_t)b * PP * 3;
        for (int j = tid; j < PP; j += 512) {
            sx[j] = pb[3 * j + 0];
            sy[j] = pb[3 * j + 1];
            sz[j] = pb[3 * j + 2];
        }
        __syncthreads();

        ull X[4], Y[4], Z[4];
        float dist[8];
#pragma unroll
        for (int p = 0; p < 4; p++) {
            int j0 = tid + (2 * p) * 512, j1 = tid + (2 * p + 1) * 512;
            PACK2(X[p], sx[j0], sx[j1]);
            PACK2(Y[p], sy[j0], sy[j1]);
            PACK2(Z[p], sz[j0], sz[j1]);
            dist[2 * p] = INFINITY; dist[2 * p + 1] = INFINITY;
        }

        if (tid == 0) g_fps[b * MM] = 0;

        int last = 0;
        for (int i = 1; i < MM; i++) {
            float lx = sx[last], ly = sy[last], lz = sz[last];
            float nlx = -lx, nly = -ly, nlz = -lz;
            ull NLX, NLY, NLZ;
            PACK2(NLX, nlx, nlx); PACK2(NLY, nly, nly); PACK2(NLZ, nlz, nlz);

#pragma unroll
            for (int p = 0; p < 4; p++) {
                // d = ((dx*dx + dy*dy) + dz*dz), no fma -> bitwise == scalar rn
                ull dx, dy, dz, mx, my, mz, t2, dd;
                ADD2(dx, X[p], NLX); ADD2(dy, Y[p], NLY); ADD2(dz, Z[p], NLZ);
                MUL2(mx, dx, dx); MUL2(my, dy, dy); MUL2(mz, dz, dz);
                ADD2(t2, mx, my); ADD2(dd, t2, mz);
                float dlo, dhi;
                UNPACK2(dlo, dhi, dd);
                dist[2 * p]     = fminf(dist[2 * p],     dlo);
                dist[2 * p + 1] = fminf(dist[2 * p + 1], dhi);
            }

            // per-thread argmax via u64 key tree: key = (dbits<<32) | ~slot.
            // dist >= 0 -> bits order-preserving; max key = max dist, tie -> min
            // slot. EXACTLY equals the sequential strict-> scan in slot order.
            ull kx[8];
#pragma unroll
            for (int k = 0; k < 8; k++)
                kx[k] = ((ull)__float_as_uint(dist[k]) << 32) |
                        (unsigned)~(unsigned)(tid + k * 512);
            ull m01 = umax64(kx[0], kx[1]), m23 = umax64(kx[2], kx[3]);
            ull m45 = umax64(kx[4], kx[5]), m67 = umax64(kx[6], kx[7]);
            ull mA = umax64(m01, m23), mB = umax64(m45, m67);
            ull kbest = umax64(mA, mB);
            unsigned vb = (unsigned)(kbest >> 32);
            unsigned bj = ~(unsigned)kbest;

            // warp argmax, first-index tie-break
            unsigned wm = __reduce_max_sync(0xffffffffu, vb);
            unsigned cj = (vb == wm) ? bj : 0xffffffffu;
            unsigned wj = __reduce_min_sync(0xffffffffu, cj);

            uint2* buf = swp + ((i & 1) << 4);
            if (lane == 0) buf[wid] = make_uint2(wm, wj);
            __syncthreads();
            // all warps redundantly reduce 16 warp results (single barrier/iter)
            uint2 e = (lane < 16) ? buf[lane] : make_uint2(0u, 0xffffffffu);
            unsigned gm  = __reduce_max_sync(0xffffffffu, e.x);
            unsigned cj2 = (e.x == gm) ? e.y : 0xffffffffu;
            unsigned gj  = __reduce_min_sync(0xffffffffu, cj2);
            last = (int)gj;
            if (tid == 0) {
                g_fps[b * MM + i] = last;
                if ((i & 127) == 127) {       // publish 128, 256, ..., 1024
                    __threadfence();
                    atomicExch(&g_prog[b], i + 1);
                }
            }
        }
    } else if (bid < BB + N_MLP_BLOCKS) {
        // ---------------- MLP (+xx) path: 256 rows per block (proven) ----------------
        float* sW = fsm;               // 8192 floats (32 KB)
        float* sF = fsm + FIN * FOUT;  // 16384 floats (64 KB)

        const int row0 = (bid - BB) * 256;

        for (int l = tid; l < FIN * FOUT; l += 512) sW[l] = W[l];
        float4* sF4 = (float4*)sF;
        const float4* feat4 = (const float4*)(feat + (size_t)row0 * FIN);
        for (int l = tid; l < 256 * (FIN / 4); l += 512) sF4[l] = feat4[l];
        __syncthreads();

        if (tid < 256) {
            float a0 = 0.f, a1 = 0.f, a2 = 0.f, a3 = 0.f;
#pragma unroll
            for (int d = 0; d < FIN / 4; d++) {
                float4 v = sF4[tid * (FIN / 4) + d];
                a0 += v.x * v.x; a1 += v.y * v.y; a2 += v.z * v.z; a3 += v.w * v.w;
            }
            g_xx[row0 + tid] = (a0 + a1) + (a2 + a3);
        }

        const int col = tid & 127;
        const int grp = tid >> 7;          // 0..3, 64 rows each
        const int rbase = grp * 64;
        const float bc = bias[col];
        float s1 = 0.f, s2 = 0.f;

        for (int r = rbase; r < rbase + 64; r += 2) {
            float a0 = bc, a1 = bc;
#pragma unroll
            for (int d4 = 0; d4 < FIN / 4; d4++) {
                float4 f0 = sF4[r * (FIN / 4) + d4];
                float4 f1 = sF4[(r + 1) * (FIN / 4) + d4];
                float w0 = sW[(d4 * 4 + 0) * FOUT + col];
                float w1 = sW[(d4 * 4 + 1) * FOUT + col];
                float w2 = sW[(d4 * 4 + 2) * FOUT + col];
                float w3 = sW[(d4 * 4 + 3) * FOUT + col];
                a0 += f0.x * w0; a0 += f0.y * w1; a0 += f0.z * w2; a0 += f0.w * w3;
                a1 += f1.x * w0; a1 += f1.y * w1; a1 += f1.z * w2; a1 += f1.w * w3;
            }
            g_h[(size_t)(row0 + r)     * FOUT + col] = a0;
            g_h[(size_t)(row0 + r + 1) * FOUT + col] = a1;
            s1 += a0 + a1;
            s2 += a0 * a0 + a1 * a1;
        }
        const int prow = (bid - BB) * 4 + grp;   // 0..1023
        g_psum[prow * FOUT + col] = s1;
        g_psq [prow * FOUT + col] = s2;

        __syncthreads();                 // all block writes done
        if (tid == 0) {
            __threadfence();
            atomicAdd(&g_mlp_done, 1);
        }
    } else {
        // ---------------- KNN quarter-chunk: 512 thr, 4 subs x 256 candidates ----------------
        char* ksm = (char*)fsm;
        float* sTile = (float*)ksm;                 // 4*32*64 f32 = 32 KB (loop phase)
        ull*   mbuf  = (ull*)ksm;                   // 64*128*8B  = 64 KB (merge phase)
        float* sxx   = (float*)(ksm + 65536);       // 128 f32

        const int kb    = bid - (BB + N_MLP_BLOCKS);  // 0..511, chunk-major
        const int chunk = kb >> 6;                    // 0..7
        const int rem   = kb & 63;
        const int b     = rem >> 2;                   // 0..15
        const int qtr   = rem & 3;                    // candidate quarter
        const int cbase = qtr * 1024;
        const int sub = tid >> 7;          // 0..3
        const int q   = tid & 127;
        const int m = chunk * 128 + q;

        // spin until dependencies are published
        if (tid == 0) {
            while (atomicAdd(&g_mlp_done, 0) < N_MLP_BLOCKS) __nanosleep(200);
            const int need = chunk * 128 + 128;
            while (atomicAdd(&g_prog[b], 0) < need) __nanosleep(200);
            __threadfence();
        }
        __syncthreads();

        const int qi = g_fps[b * MM + m];
        const float4* qrow = (const float4*)(feat + ((size_t)b * PP + qi) * FIN);
        ull qp[32];
#pragma unroll
        for (int d = 0; d < FIN / 4; d++) {
            float4 f = qrow[d];
            PACK2(qp[2 * d],     f.x, f.y);
            PACK2(qp[2 * d + 1], f.z, f.w);
        }
        const float qq = g_xx[(size_t)b * PP + qi];

        float topv[KK];
        int   topi[KK];
#pragma unroll
        for (int s = 0; s < KK; s++) { topv[s] = INFINITY; topi[s] = 0x7fffffff; }
        float worst = INFINITY;

        const float4* fb4 = (const float4*)(feat + (size_t)b * PP * FIN);
        float4* sT4 = (float4*)sTile;

        for (int p0 = 0; p0 < 256; p0 += 32) {
            __syncthreads();
            // cooperative tile load: pass i loads sub i's 32 rows
#pragma unroll
            for (int i = 0; i < 4; i++) {
                int row = tid >> 4;          // 0..31
                int c4  = tid & 15;
                int grow = cbase + i * 256 + p0 + row;
                sT4[i * 512 + tid] = fb4[(size_t)grow * (FIN / 4) + c4];
            }
            if (tid < 128) {
                int ss = tid >> 5, r = tid & 31;
                sxx[tid] = g_xx[(size_t)b * PP + cbase + ss * 256 + p0 + r];
            }
            __syncthreads();

#pragma unroll 2
            for (int c = 0; c < 32; c++) {
                const ulonglong2* xr = (const ulonglong2*)(sTile + (size_t)(sub * 32 + c) * FIN);
                ull a01 = 0ull, a23 = 0ull;
#pragma unroll
                for (int d = 0; d < FIN / 4; d++) {
                    ulonglong2 xv = xr[d];
                    FMA2(a01, qp[2 * d],     xv.x);
                    FMA2(a23, qp[2 * d + 1], xv.y);
                }
                float a0, a1, a2, a3;
                UNPACK2(a0, a1, a01);
                UNPACK2(a2, a3, a23);
                float dot = (a0 + a1) + (a2 + a3);
                float d2  = (qq - 2.0f * dot) + sxx[sub * 32 + c];
                if (d2 < worst) {
                    int cand = cbase + sub * 256 + p0 + c;
                    float mv = topv[0]; int mi = topi[0]; int msl = 0;
#pragma unroll
                    for (int s = 1; s < KK; s++) {
                        bool better = (topv[s] > mv) || (topv[s] == mv && topi[s] > mi);
                        if (better) { mv = topv[s]; mi = topi[s]; msl = s; }
                    }
#pragma unroll
                    for (int s = 0; s < KK; s++) {
                        if (s == msl) { topv[s] = d2; topi[s] = cand; }
                    }
                    worst = topv[0];
#pragma unroll
                    for (int s = 1; s < KK; s++) worst = fmaxf(worst, topv[s]);
                }
            }
        }

        // ---- exact merge across 4 subs: key = (monotone(d2) << 32) | idx ----
        __syncthreads();   // tile reads done; reuse smem as mbuf
#pragma unroll
        for (int s = 0; s < KK; s++) {
            unsigned v = __float_as_uint(topv[s]);
            unsigned u = (v & 0x80000000u) ? ~v : (v | 0x80000000u);
            mbuf[(size_t)(sub * KK + s) * 128 + q] = ((ull)u << 32) | (unsigned)topi[s];
        }
        __syncthreads();

        if (sub == 0) {
            size_t kbase = (size_t)(b * MM + m) * 64 + qtr * 16;
#pragma unroll 1
            for (int k = 0; k < KK; k++) {       // emits ascending key order
                ull best = 0xffffffffffffffffull; int jb = 0;
                for (int j = 0; j < 64; j++) {
                    ull e = mbuf[(size_t)j * 128 + q];
                    if (e < best) { best = e; jb = j; }
                }
                mbuf[(size_t)jb * 128 + q] = 0xffffffffffffffffull;
                g_keys[kbase + k] = best;
            }
        }
    }
}

// Deterministic BN stat reduction: one block per column, fixed-order tree.
__global__ void bn_reduce_kernel()
{
    __shared__ float r1[256], r2[256];
    const int col = blockIdx.x;
    const int tid = threadIdx.x;
    float s1 = 0.f, s2 = 0.f;
    for (int i = tid; i < 1024; i += 256) {
        s1 += g_psum[i * FOUT + col];
        s2 += g_psq [i * FOUT + col];
    }
    r1[tid] = s1; r2[tid] = s2;
    __syncthreads();
    for (int off = 128; off > 0; off >>= 1) {
        if (tid < off) { r1[tid] += r1[tid + off]; r2[tid] += r2[tid + off]; }
        __syncthreads();
    }
    if (tid == 0) {
        float mean = r1[0] / (float)NN;
        float var  = r2[0] / (float)NN - mean * mean;
        if (var < 0.f) var = 0.f;
        g_mean[col] = mean;
        g_var [col] = var;
    }
}

// ============================================================
// Gather: exact 4-pointer merge of four sorted quarter key-lists,
// then fused BN + ReLU + max-pool over the K neighbors.
// ============================================================
__global__ void gather_kernel(const float* __restrict__ pos,
                              const float* __restrict__ gamma,
                              const float* __restrict__ beta,
                              float* __restrict__ out,
                              int out_size)
{
    __shared__ ull skey[64];
    __shared__ int sidx[KK];
    __shared__ int sfps;
    const int q   = blockIdx.x;
    const int b   = q >> 10;
    const int tid = threadIdx.x;

    if (tid < 64) skey[tid] = g_keys[(size_t)q * 64 + tid];
    if (tid == 64) sfps = g_fps[q];
    __syncthreads();

    if (tid == 0) {
        // 4-pointer merge of 4 sorted lists of 16 (ascending keys)
        ull c0 = skey[0], c1 = skey[16], c2 = skey[32], c3 = skey[48];
        int h0 = 0, h1 = 0, h2 = 0, h3 = 0;
#pragma unroll
        for (int k = 0; k < KK; k++) {
            ull mn = c0; int which = 0;
            if (c1 < mn) { mn = c1; which = 1; }
            if (c2 < mn) { mn = c2; which = 2; }
            if (c3 < mn) { mn = c3; which = 3; }
            sidx[k] = (int)(unsigned)(mn & 0xffffffffu);
            if (which == 0) { h0++; c0 = (h0 < KK) ? skey[h0]      : 0xffffffffffffffffull; }
            else if (which == 1) { h1++; c1 = (h1 < KK) ? skey[16 + h1] : 0xffffffffffffffffull; }
            else if (which == 2) { h2++; c2 = (h2 < KK) ? skey[32 + h2] : 0xffffffffffffffffull; }
            else { h3++; c3 = (h3 < KK) ? skey[48 + h3] : 0xffffffffffffffffull; }
        }
    }
    __syncthreads();

    const int col = tid;
    float mean = g_mean[col];
    float rstd = rsqrtf(g_var[col] + BN_EPS);
    float ga = gamma[col], be = beta[col];
    const float* hb = g_h + (size_t)b * PP * FOUT;

    float mx = -INFINITY;
#pragma unroll
    for (int k = 0; k < KK; k++) {
        float v = hb[(size_t)sidx[k] * FOUT + col];
        v = (v - mean) * rstd * ga + be;
        v = fmaxf(v, 0.f);
        mx = fmaxf(mx, v);
    }
    out[(size_t)q * FOUT + col] = mx;

    if (out_size >= TOTAL_OUT) {
        if (tid < 3) out[OFF_P + q * 3 + tid] = pos[((size_t)b * PP + sfps) * 3 + tid];
        if (tid == 3) out[OFF_B + q] = (float)b;
    }
}

// ============================================================
extern "C" void kernel_launch(void* const* d_in, const int* in_sizes, int n_in,
                              void* d_out, int out_size)
{
    const float* pos   = (const float*)d_in[0];
    const float* feat  = (const float*)d_in[1];
    // d_in[2] = batch_indices (unused: clouds are sorted & equal-sized)
    const float* W     = (const float*)d_in[3];
    const float* bias  = (const float*)d_in[4];
    const float* gamma = (const float*)d_in[5];
    const float* beta  = (const float*)d_in[6];
    float* out = (float*)d_out;

    // mega smem: max(FPS 48.3KB, MLP 96KB, KNN 64.5KB) = 96 KB
    const int mega_smem = (FIN * FOUT + 256 * FIN) * sizeof(float);   // 98304
    cudaFuncSetAttribute(mega_kernel, cudaFuncAttributeMaxDynamicSharedMemorySize, mega_smem);

    init_kernel<<<1, 32>>>();
    mega_kernel<<<MEGA_BLOCKS, 512, mega_smem>>>(pos, feat, W, bias);
    bn_reduce_kernel<<<FOUT, 256>>>();
    gather_kernel<<<BB * MM, 128>>>(pos, gamma, beta, out, out_size);
}

// round 16
// speedup vs baseline: 1.0352x; 1.0352x over previous
#include <cuda_runtime.h>
#include <cuda_bf16.h>
#include <math.h>

// Problem constants
#define BB   16
#define PP   4096
#define MM   1024
#define KK   16
#define FIN  64
#define FOUT 128
#define NN   (BB * PP)          // 65536
#define BN_EPS 1e-5f

#define OFF_P  (BB * MM * FOUT)            // 2097152
#define OFF_B  (OFF_P + BB * MM * 3)       // 2146304
#define TOTAL_OUT (OFF_B + BB * MM)        // 2162688

#define N_MLP_BLOCKS 256
#define N_KNN_BLOCKS 256                    // 8 chunks x 16 clouds x 2 halves
#define MEGA_BLOCKS  (BB + N_MLP_BLOCKS + N_KNN_BLOCKS)   // 528

// f32x2 packed ops (sm_103a): two independent rn-rounded fp32 ops ->
// bitwise identical to the scalar sequences they replace.
#define PACK2(o, lo, hi)  asm("mov.b64 %0, {%1, %2};" : "=l"(o) : "f"(lo), "f"(hi))
#define UNPACK2(lo, hi, i) asm("mov.b64 {%0, %1}, %2;" : "=f"(lo), "=f"(hi) : "l"(i))
#define FMA2(acc, a, b)   asm("fma.rn.f32x2 %0, %1, %2, %0;" : "+l"(acc) : "l"(a), "l"(b))
#define ADD2(o, a, b)     asm("add.rn.f32x2 %0, %1, %2;" : "=l"(o) : "l"(a), "l"(b))
#define MUL2(o, a, b)     asm("mul.rn.f32x2 %0, %1, %2;" : "=l"(o) : "l"(a), "l"(b))

typedef unsigned long long ull;

static __device__ __forceinline__ ull umax64(ull a, ull b) { return a > b ? a : b; }

// -------- scratch (static device globals; no allocation allowed) --------
__device__ int   g_fps[BB * MM];
__device__ ull   g_keys[(size_t)BB * MM * 32];  // per query: 2 halves x 16 sorted keys
__device__ float g_h[(size_t)NN * FOUT];        // 33.5 MB pre-BN activations
__device__ float g_psum[1024 * FOUT];           // 1024 x 128 partial sums (64 rows each)
__device__ float g_psq [1024 * FOUT];
__device__ float g_mean[FOUT];
__device__ float g_var [FOUT];
__device__ float g_xx[NN];                      // per-point sum(x*x) in feature space
// cross-block progress (reset by init kernel every call)
__device__ int   g_prog[BB];                    // fps indices published per cloud
__device__ int   g_mlp_done;                    // completed mlp blocks

__global__ void init_kernel()
{
    int t = threadIdx.x;
    if (t < BB) g_prog[t] = 0;
    if (t == 31) g_mlp_done = 0;
}

// ============================================================
// Mega kernel, 512 threads/block:
//   blocks [0,16)    : FPS (one cloud each, publishes progress/128)
//   blocks [16,272)  : MLP (+xx) on 256 rows each, signals done
//   blocks [272,528) : KNN half-chunk (128 queries x 2048 candidates),
//                      spins on progress, emits sorted top-16 keys.
// ============================================================
__global__ void __launch_bounds__(512) mega_kernel(
    const float* __restrict__ pos,
    const float* __restrict__ feat,
    const float* __restrict__ W,
    const float* __restrict__ bias)
{
    extern __shared__ float fsm[];
    const int tid = threadIdx.x;
    const int bid = blockIdx.x;

    if (bid < BB) {
        // ---------------- FPS path: 512 thr, 8 pts/thread ----------------
        float* sx = fsm;
        float* sy = fsm + PP;
        float* sz = fsm + 2 * PP;
        uint2* swp = (uint2*)(fsm + 3 * PP);   // double-buffered: 2 x 16

        const int b    = bid;
        const int lane = tid & 31;
        const int wid  = tid >> 5;             // 0..15

        const float* pb = pos + (size_t)b * PP * 3;
        for (int j = tid; j < PP; j += 512) {
            sx[j] = pb[3 * j + 0];
            sy[j] = pb[3 * j + 1];
            sz[j] = pb[3 * j + 2];
        }
        __syncthreads();

        ull X[4], Y[4], Z[4];
        float dist[8];
#pragma unroll
        for (int p = 0; p < 4; p++) {
            int j0 = tid + (2 * p) * 512, j1 = tid + (2 * p + 1) * 512;
            PACK2(X[p], sx[j0], sx[j1]);
            PACK2(Y[p], sy[j0], sy[j1]);
            PACK2(Z[p], sz[j0], sz[j1]);
            dist[2 * p] = INFINITY; dist[2 * p + 1] = INFINITY;
        }

        if (tid == 0) g_fps[b * MM] = 0;

        int last = 0;
        for (int i = 1; i < MM; i++) {
            float lx = sx[last], ly = sy[last], lz = sz[last];
            float nlx = -lx, nly = -ly, nlz = -lz;
            ull NLX, NLY, NLZ;
            PACK2(NLX, nlx, nlx); PACK2(NLY, nly, nly); PACK2(NLZ, nlz, nlz);

#pragma unroll
            for (int p = 0; p < 4; p++) {
                // d = ((dx*dx + dy*dy) + dz*dz), no fma -> bitwise == scalar rn
                ull dx, dy, dz, mx, my, mz, t2, dd;
                ADD2(dx, X[p], NLX); ADD2(dy, Y[p], NLY); ADD2(dz, Z[p], NLZ);
                MUL2(mx, dx, dx); MUL2(my, dy, dy); MUL2(mz, dz, dz);
                ADD2(t2, mx, my); ADD2(dd, t2, mz);
                float dlo, dhi;
                UNPACK2(dlo, dhi, dd);
                dist[2 * p]     = fminf(dist[2 * p],     dlo);
                dist[2 * p + 1] = fminf(dist[2 * p + 1], dhi);
            }

            // per-thread argmax via u64 key tree: key = (dbits<<32) | ~slot.
            // dist >= 0 -> bits order-preserving; max key = max dist, tie -> min
            // slot. EXACTLY equals the sequential strict-> scan in slot order.
            ull kx[8];
#pragma unroll
            for (int k = 0; k < 8; k++)
                kx[k] = ((ull)__float_as_uint(dist[k]) << 32) |
                        (unsigned)~(unsigned)(tid + k * 512);
            ull m01 = umax64(kx[0], kx[1]), m23 = umax64(kx[2], kx[3]);
            ull m45 = umax64(kx[4], kx[5]), m67 = umax64(kx[6], kx[7]);
            ull mA = umax64(m01, m23), mB = umax64(m45, m67);
            ull kbest = umax64(mA, mB);
            unsigned vb = (unsigned)(kbest >> 32);
            unsigned bj = ~(unsigned)kbest;

            // warp argmax, first-index tie-break
            unsigned wm = __reduce_max_sync(0xffffffffu, vb);
            unsigned cj = (vb == wm) ? bj : 0xffffffffu;
            unsigned wj = __reduce_min_sync(0xffffffffu, cj);

            uint2* buf = swp + ((i & 1) << 4);
            if (lane == 0) buf[wid] = make_uint2(wm, wj);
            __syncthreads();
            // all warps redundantly reduce 16 warp results (single barrier/iter)
            uint2 e = (lane < 16) ? buf[lane] : make_uint2(0u, 0xffffffffu);
            unsigned gm  = __reduce_max_sync(0xffffffffu, e.x);
            unsigned cj2 = (e.x == gm) ? e.y : 0xffffffffu;
            unsigned gj  = __reduce_min_sync(0xffffffffu, cj2);
            last = (int)gj;
            if (tid == 0) {
                g_fps[b * MM + i] = last;
                if ((i & 127) == 127) {       // publish 128, 256, ..., 1024
                    __threadfence();
                    atomicExch(&g_prog[b], i + 1);
                }
            }
        }
    } else if (bid < BB + N_MLP_BLOCKS) {
        // ---------------- MLP (+xx) path: 256 rows per block (proven) ----------------
        float* sW = fsm;               // 8192 floats (32 KB)
        float* sF = fsm + FIN * FOUT;  // 16384 floats (64 KB)

        const int row0 = (bid - BB) * 256;

        for (int l = tid; l < FIN * FOUT; l += 512) sW[l] = W[l];
        float4* sF4 = (float4*)sF;
        const float4* feat4 = (const float4*)(feat + (size_t)row0 * FIN);
        for (int l = tid; l < 256 * (FIN / 4); l += 512) sF4[l] = feat4[l];
        __syncthreads();

        if (tid < 256) {
            float a0 = 0.f, a1 = 0.f, a2 = 0.f, a3 = 0.f;
#pragma unroll
            for (int d = 0; d < FIN / 4; d++) {
                float4 v = sF4[tid * (FIN / 4) + d];
                a0 += v.x * v.x; a1 += v.y * v.y; a2 += v.z * v.z; a3 += v.w * v.w;
            }
            g_xx[row0 + tid] = (a0 + a1) + (a2 + a3);
        }

        const int col = tid & 127;
        const int grp = tid >> 7;          // 0..3, 64 rows each
        const int rbase = grp * 64;
        const float bc = bias[col];
        float s1 = 0.f, s2 = 0.f;

        for (int r = rbase; r < rbase + 64; r += 2) {
            float a0 = bc, a1 = bc;
#pragma unroll
            for (int d4 = 0; d4 < FIN / 4; d4++) {
                float4 f0 = sF4[r * (FIN / 4) + d4];
                float4 f1 = sF4[(r + 1) * (FIN / 4) + d4];
                float w0 = sW[(d4 * 4 + 0) * FOUT + col];
                float w1 = sW[(d4 * 4 + 1) * FOUT + col];
                float w2 = sW[(d4 * 4 + 2) * FOUT + col];
                float w3 = sW[(d4 * 4 + 3) * FOUT + col];
                a0 += f0.x * w0; a0 += f0.y * w1; a0 += f0.z * w2; a0 += f0.w * w3;
                a1 += f1.x * w0; a1 += f1.y * w1; a1 += f1.z * w2; a1 += f1.w * w3;
            }
            g_h[(size_t)(row0 + r)     * FOUT + col] = a0;
            g_h[(size_t)(row0 + r + 1) * FOUT + col] = a1;
            s1 += a0 + a1;
            s2 += a0 * a0 + a1 * a1;
        }
        const int prow = (bid - BB) * 4 + grp;   // 0..1023
        g_psum[prow * FOUT + col] = s1;
        g_psq [prow * FOUT + col] = s2;

        __syncthreads();                 // all block writes done
        if (tid == 0) {
            __threadfence();
            atomicAdd(&g_mlp_done, 1);
        }
    } else {
        // ---------------- KNN half-chunk: 512 thr, 4 subs x 512 candidates ----------------
        char* ksm = (char*)fsm;
        float* sTile = (float*)ksm;                 // 4*32*64 f32 = 32 KB (loop phase)
        ull*   mbuf  = (ull*)ksm;                   // 64*128*8B  = 64 KB (merge phase)
        float* sxx   = (float*)(ksm + 65536);       // 128 f32

        const int kb    = bid - (BB + N_MLP_BLOCKS);  // 0..255, chunk-major
        const int chunk = kb >> 5;                    // 0..7
        const int rem   = kb & 31;
        const int b     = rem >> 1;                   // 0..15
        const int h     = rem & 1;                    // candidate half
        const int cbase = h * 2048;
        const int sub = tid >> 7;          // 0..3
        const int q   = tid & 127;
        const int m = chunk * 128 + q;

        // spin until dependencies are published
        if (tid == 0) {
            while (atomicAdd(&g_mlp_done, 0) < N_MLP_BLOCKS) __nanosleep(200);
            const int need = chunk * 128 + 128;
            while (atomicAdd(&g_prog[b], 0) < need) __nanosleep(200);
            __threadfence();
        }
        __syncthreads();

        const int qi = g_fps[b * MM + m];
        const float4* qrow = (const float4*)(feat + ((size_t)b * PP + qi) * FIN);
        ull qp[32];
#pragma unroll
        for (int d = 0; d < FIN / 4; d++) {
            float4 f = qrow[d];
            PACK2(qp[2 * d],     f.x, f.y);
            PACK2(qp[2 * d + 1], f.z, f.w);
        }
        const float qq = g_xx[(size_t)b * PP + qi];

        float topv[KK];
        int   topi[KK];
#pragma unroll
        for (int s = 0; s < KK; s++) { topv[s] = INFINITY; topi[s] = 0x7fffffff; }
        float worst = INFINITY;

        const float4* fb4 = (const float4*)(feat + (size_t)b * PP * FIN);
        float4* sT4 = (float4*)sTile;

        for (int p0 = 0; p0 < 512; p0 += 32) {
            __syncthreads();
            // cooperative tile load: pass i loads sub i's 32 rows
#pragma unroll
            for (int i = 0; i < 4; i++) {
                int row = tid >> 4;          // 0..31
                int c4  = tid & 15;
                int grow = cbase + i * 512 + p0 + row;
                sT4[i * 512 + tid] = fb4[(size_t)grow * (FIN / 4) + c4];
            }
            if (tid < 128) {
                int ss = tid >> 5, r = tid & 31;
                sxx[tid] = g_xx[(size_t)b * PP + cbase + ss * 512 + p0 + r];
            }
            __syncthreads();

#pragma unroll 2
            for (int c = 0; c < 32; c++) {
                const ulonglong2* xr = (const ulonglong2*)(sTile + (size_t)(sub * 32 + c) * FIN);
                ull a01 = 0ull, a23 = 0ull;
#pragma unroll
                for (int d = 0; d < FIN / 4; d++) {
                    ulonglong2 xv = xr[d];
                    FMA2(a01, qp[2 * d],     xv.x);
                    FMA2(a23, qp[2 * d + 1], xv.y);
                }
                float a0, a1, a2, a3;
                UNPACK2(a0, a1, a01);
                UNPACK2(a2, a3, a23);
                float dot = (a0 + a1) + (a2 + a3);
                float d2  = (qq - 2.0f * dot) + sxx[sub * 32 + c];
                if (d2 < worst) {
                    int cand = cbase + sub * 512 + p0 + c;
                    float mv = topv[0]; int mi = topi[0]; int msl = 0;
#pragma unroll
                    for (int s = 1; s < KK; s++) {
                        bool better = (topv[s] > mv) || (topv[s] == mv && topi[s] > mi);
                        if (better) { mv = topv[s]; mi = topi[s]; msl = s; }
                    }
#pragma unroll
                    for (int s = 0; s < KK; s++) {
                        if (s == msl) { topv[s] = d2; topi[s] = cand; }
                    }
                    worst = topv[0];
#pragma unroll
                    for (int s = 1; s < KK; s++) worst = fmaxf(worst, topv[s]);
                }
            }
        }

        // ---- exact merge across 4 subs: key = (monotone(d2) << 32) | idx ----
        __syncthreads();   // tile reads done; reuse smem as mbuf
#pragma unroll
        for (int s = 0; s < KK; s++) {
            unsigned v = __float_as_uint(topv[s]);
            unsigned u = (v & 0x80000000u) ? ~v : (v | 0x80000000u);
            mbuf[(size_t)(sub * KK + s) * 128 + q] = ((ull)u << 32) | (unsigned)topi[s];
        }
        __syncthreads();

        if (sub == 0) {
            size_t kbase = (size_t)(b * MM + m) * 32 + h * 16;
#pragma unroll 1
            for (int k = 0; k < KK; k++) {       // emits ascending key order
                ull best = 0xffffffffffffffffull; int jb = 0;
                for (int j = 0; j < 64; j++) {
                    ull e = mbuf[(size_t)j * 128 + q];
                    if (e < best) { best = e; jb = j; }
                }
                mbuf[(size_t)jb * 128 + q] = 0xffffffffffffffffull;
                g_keys[kbase + k] = best;
            }
        }
    }
}

// Deterministic BN stat reduction: one block per column, fixed-order tree.
__global__ void bn_reduce_kernel()
{
    __shared__ float r1[256], r2[256];
    const int col = blockIdx.x;
    const int tid = threadIdx.x;
    float s1 = 0.f, s2 = 0.f;
    for (int i = tid; i < 1024; i += 256) {
        s1 += g_psum[i * FOUT + col];
        s2 += g_psq [i * FOUT + col];
    }
    r1[tid] = s1; r2[tid] = s2;
    __syncthreads();
    for (int off = 128; off > 0; off >>= 1) {
        if (tid < off) { r1[tid] += r1[tid + off]; r2[tid] += r2[tid + off]; }
        __syncthreads();
    }
    if (tid == 0) {
        float mean = r1[0] / (float)NN;
        float var  = r2[0] / (float)NN - mean * mean;
        if (var < 0.f) var = 0.f;
        g_mean[col] = mean;
        g_var [col] = var;
    }
}

// ============================================================
// Gather: exact 2-pointer merge of the two sorted half key-lists,
// then fused BN + ReLU + max-pool over the K neighbors.
// ============================================================
__global__ void gather_kernel(const float* __restrict__ pos,
                              const float* __restrict__ gamma,
                              const float* __restrict__ beta,
                              float* __restrict__ out,
                              int out_size)
{
    __shared__ ull skey[32];
    __shared__ int sidx[KK];
    __shared__ int sfps;
    const int q   = blockIdx.x;
    const int b   = q >> 10;
    const int tid = threadIdx.x;

    if (tid < 32) skey[tid] = g_keys[(size_t)q * 32 + tid];
    if (tid == 32) sfps = g_fps[q];
    __syncthreads();

    if (tid == 0) {
        ull c0 = skey[0], c1 = skey[16];
        int h0 = 0, h1 = 0;
#pragma unroll
        for (int k = 0; k < KK; k++) {
            bool take0 = (c0 < c1);
            ull w = take0 ? c0 : c1;
            sidx[k] = (int)(unsigned)(w & 0xffffffffu);
            if (take0) {
                h0++;
                c0 = (h0 < KK) ? skey[h0] : 0xffffffffffffffffull;
            } else {
                h1++;
                c1 = (h1 < KK) ? skey[KK + h1] : 0xffffffffffffffffull;
            }
        }
    }
    __syncthreads();

    const int col = tid;
    float mean = g_mean[col];
    float rstd = rsqrtf(g_var[col] + BN_EPS);
    float ga = gamma[col], be = beta[col];
    const float* hb = g_h + (size_t)b * PP * FOUT;

    float mx = -INFINITY;
#pragma unroll
    for (int k = 0; k < KK; k++) {
        float v = hb[(size_t)sidx[k] * FOUT + col];
        v = (v - mean) * rstd * ga + be;
        v = fmaxf(v, 0.f);
        mx = fmaxf(mx, v);
    }
    out[(size_t)q * FOUT + col] = mx;

    if (out_size >= TOTAL_OUT) {
        if (tid < 3) out[OFF_P + q * 3 + tid] = pos[((size_t)b * PP + sfps) * 3 + tid];
        if (tid == 3) out[OFF_B + q] = (float)b;
    }
}

// ============================================================
extern "C" void kernel_launch(void* const* d_in, const int* in_sizes, int n_in,
                              void* d_out, int out_size)
{
    const float* pos   = (const float*)d_in[0];
    const float* feat  = (const float*)d_in[1];
    // d_in[2] = batch_indices (unused: clouds are sorted & equal-sized)
    const float* W     = (const float*)d_in[3];
    const float* bias  = (const float*)d_in[4];
    const float* gamma = (const float*)d_in[5];
    const float* beta  = (const float*)d_in[6];
    float* out = (float*)d_out;

    // mega smem: max(FPS 48.3KB, MLP 96KB, KNN 64.5KB) = 96 KB
    const int mega_smem = (FIN * FOUT + 256 * FIN) * sizeof(float);   // 98304
    cudaFuncSetAttribute(mega_kernel, cudaFuncAttributeMaxDynamicSharedMemorySize, mega_smem);

    init_kernel<<<1, 32>>>();
    mega_kernel<<<MEGA_BLOCKS, 512, mega_smem>>>(pos, feat, W, bias);
    bn_reduce_kernel<<<FOUT, 256>>>();
    gather_kernel<<<BB * MM, 128>>>(pos, gamma, beta, out, out_size);
}